// round 4
// baseline (speedup 1.0000x reference)
#include <cuda_runtime.h>
#include <math.h>
#include <stdint.h>

#define BB   64
#define SS   1024
#define DD   128
#define HH   256
#define M_ROWS (BB*SS)          // 65536
#define NPROJ  (4*HH)           // 1024
#define N2H    (2*HH)           // 512

typedef unsigned long long u64;

// ---------------- device scratch ----------------
__device__ __align__(16) float g_P[(size_t)M_ROWS * NPROJ];
__device__ __align__(16) float g_Hout[(size_t)M_ROWS * N2H];
__device__ __align__(16) float g_Wcat[DD * NPROJ];
__device__ __align__(16) float g_bcat[NPROJ];
__device__ __align__(16) float g_spart[4 * M_ROWS];
__device__ __align__(16) float g_attn[M_ROWS];
__device__ __align__(16) float g_cpart[8 * BB * N2H];

// ---------------- packed fp32 helpers ----------------
#define FMA2(d, a, b) asm("fma.rn.f32x2 %0, %1, %2, %0;" : "+l"(d) : "l"(a), "l"(b))
#define ADD2(d, a, b) asm("add.rn.f32x2 %0, %1, %2;" : "=l"(d) : "l"(a), "l"(b))
#define PACK2(d, lo, hi) asm("mov.b64 %0, {%1, %2};" : "=l"(d) : "f"(lo), "f"(hi))
#define UNPACK2(lo, hi, d) asm("mov.b64 {%0, %1}, %2;" : "=f"(lo), "=f"(hi) : "l"(d))

__device__ __forceinline__ float fast_sigmoid(float x) {
    return __fdividef(1.f, 1.f + __expf(-x));
}
__device__ __forceinline__ float fast_tanh(float x) {
    return 1.f - __fdividef(2.f, __expf(2.f * x) + 1.f);
}

// ---------------- weight packing ----------------
__global__ void pack_weights(const float* __restrict__ Wzf, const float* __restrict__ Whf,
                             const float* __restrict__ Wzb, const float* __restrict__ Whb,
                             const float* __restrict__ bzf, const float* __restrict__ bhf,
                             const float* __restrict__ bzb, const float* __restrict__ bhb) {
    int idx = blockIdx.x * 256 + threadIdx.x;
    if (idx < DD * NPROJ) {
        int k = idx >> 10;
        int n = idx & 1023;
        int sel = n >> 8;
        int c = n & 255;
        const float* W = (sel == 0) ? Wzf : (sel == 1) ? Whf : (sel == 2) ? Wzb : Whb;
        g_Wcat[idx] = W[k * HH + c];
    }
    if (idx < NPROJ) {
        int sel = idx >> 8;
        int c = idx & 255;
        const float* bp = (sel == 0) ? bzf : (sel == 1) ? bhf : (sel == 2) ? bzb : bhb;
        g_bcat[idx] = bp[c];
    }
}

// ---------------- 128x128 SGEMM with f32x2 + register pipelining ----------------
// As: transposed + duplicated (a,a) pairs: word index k*268 + m*2, 16 k-rows.
// Bs: natural 16x128 rows; columns read as (c, c+1) u64 pairs.
// MODE 0: C = A@B + bias.  MODE 1: spart[by][row] = sum_c tanh(.)*w2[c].
template<int K, int N, int MODE>
__device__ __forceinline__ void gemm128_body(const float* __restrict__ A, const float* __restrict__ B,
                                             const float* __restrict__ bias, float* __restrict__ C,
                                             const float* __restrict__ w2, float* __restrict__ spart) {
    __shared__ __align__(16) float As[16 * 268 + 8];
    __shared__ __align__(16) float Bs[16][132];
    __shared__ float red[128][17];
    const int tid = threadIdx.x;
    const int m0 = blockIdx.x * 128;
    const int n0 = blockIdx.y * 128;
    const int tr = tid >> 4;
    const int tc = tid & 15;
    const int arow = tid >> 2;          // A stage rows: arow, arow+64
    const int akq  = (tid & 3) * 4;     // A stage k-quad
    const int bkr  = tid >> 5;          // B stage k rows: bkr, bkr+8
    const int bnq  = (tid & 31) * 4;

    u64 accp[8][4];
#pragma unroll
    for (int r = 0; r < 8; ++r)
#pragma unroll
        for (int p = 0; p < 4; ++p) accp[r][p] = 0ull;

    const int NC = K / 16;
    float4 a0s = *(const float4*)&A[(size_t)(m0 + arow) * K + akq];
    float4 a1s = *(const float4*)&A[(size_t)(m0 + arow + 64) * K + akq];
    float4 b0s = *(const float4*)&B[(size_t)bkr * N + n0 + bnq];
    float4 b1s = *(const float4*)&B[(size_t)(bkr + 8) * N + n0 + bnq];

    for (int c = 0; c < NC; ++c) {
        __syncthreads();
        // store staged tiles
        {
            u64 p;
            PACK2(p, a0s.x, a0s.x); *(u64*)&As[(akq + 0) * 268 + arow * 2] = p;
            PACK2(p, a0s.y, a0s.y); *(u64*)&As[(akq + 1) * 268 + arow * 2] = p;
            PACK2(p, a0s.z, a0s.z); *(u64*)&As[(akq + 2) * 268 + arow * 2] = p;
            PACK2(p, a0s.w, a0s.w); *(u64*)&As[(akq + 3) * 268 + arow * 2] = p;
            PACK2(p, a1s.x, a1s.x); *(u64*)&As[(akq + 0) * 268 + (arow + 64) * 2] = p;
            PACK2(p, a1s.y, a1s.y); *(u64*)&As[(akq + 1) * 268 + (arow + 64) * 2] = p;
            PACK2(p, a1s.z, a1s.z); *(u64*)&As[(akq + 2) * 268 + (arow + 64) * 2] = p;
            PACK2(p, a1s.w, a1s.w); *(u64*)&As[(akq + 3) * 268 + (arow + 64) * 2] = p;
            *(float4*)&Bs[bkr][bnq] = b0s;
            *(float4*)&Bs[bkr + 8][bnq] = b1s;
        }
        // prefetch next chunk into regs (latency hidden under compute)
        if (c + 1 < NC) {
            int kb = (c + 1) * 16;
            a0s = *(const float4*)&A[(size_t)(m0 + arow) * K + kb + akq];
            a1s = *(const float4*)&A[(size_t)(m0 + arow + 64) * K + kb + akq];
            b0s = *(const float4*)&B[(size_t)(kb + bkr) * N + n0 + bnq];
            b1s = *(const float4*)&B[(size_t)(kb + bkr + 8) * N + n0 + bnq];
        }
        __syncthreads();
#pragma unroll
        for (int k = 0; k < 16; ++k) {
            const u64* ad = (const u64*)&As[k * 268 + tr * 16];
            ulonglong2 ad0 = *(const ulonglong2*)(ad + 0);
            ulonglong2 ad1 = *(const ulonglong2*)(ad + 2);
            ulonglong2 ad2 = *(const ulonglong2*)(ad + 4);
            ulonglong2 ad3 = *(const ulonglong2*)(ad + 6);
            const u64* bp = (const u64*)&Bs[k][tc * 8];
            ulonglong2 b01 = *(const ulonglong2*)(bp + 0);
            ulonglong2 b23 = *(const ulonglong2*)(bp + 2);
            u64 ar[8] = {ad0.x, ad0.y, ad1.x, ad1.y, ad2.x, ad2.y, ad3.x, ad3.y};
            u64 bpr[4] = {b01.x, b01.y, b23.x, b23.y};
#pragma unroll
            for (int r = 0; r < 8; ++r)
#pragma unroll
                for (int p = 0; p < 4; ++p)
                    FMA2(accp[r][p], ar[r], bpr[p]);
        }
    }

    float4 bb0 = *(const float4*)&bias[n0 + tc * 8];
    float4 bb1 = *(const float4*)&bias[n0 + tc * 8 + 4];
    float bv[8] = {bb0.x, bb0.y, bb0.z, bb0.w, bb1.x, bb1.y, bb1.z, bb1.w};

    if (MODE == 0) {
#pragma unroll
        for (int r = 0; r < 8; ++r) {
            float e[8];
#pragma unroll
            for (int p = 0; p < 4; ++p) UNPACK2(e[2 * p], e[2 * p + 1], accp[r][p]);
            float* cp = &C[(size_t)(m0 + tr * 8 + r) * N + n0 + tc * 8];
            *(float4*)cp = make_float4(e[0] + bv[0], e[1] + bv[1], e[2] + bv[2], e[3] + bv[3]);
            *(float4*)(cp + 4) = make_float4(e[4] + bv[4], e[5] + bv[5], e[6] + bv[6], e[7] + bv[7]);
        }
    } else {
        float4 w20 = *(const float4*)&w2[n0 + tc * 8];
        float4 w21 = *(const float4*)&w2[n0 + tc * 8 + 4];
        float wv[8] = {w20.x, w20.y, w20.z, w20.w, w21.x, w21.y, w21.z, w21.w};
#pragma unroll
        for (int r = 0; r < 8; ++r) {
            float e[8];
#pragma unroll
            for (int p = 0; p < 4; ++p) UNPACK2(e[2 * p], e[2 * p + 1], accp[r][p]);
            float s = 0.f;
#pragma unroll
            for (int q = 0; q < 8; ++q)
                s = fmaf(fast_tanh(e[q] + bv[q]), wv[q], s);
            red[tr * 8 + r][tc] = s;
        }
        __syncthreads();
        if (tid < 128) {
            float s = 0.f;
#pragma unroll
            for (int q = 0; q < 16; ++q) s += red[tid][q];
            spart[(size_t)blockIdx.y * M_ROWS + m0 + tid] = s;
        }
    }
}

__global__ void __launch_bounds__(256, 2) gemm_proj_kernel(const float* __restrict__ x) {
    gemm128_body<DD, NPROJ, 0>(x, g_Wcat, g_bcat, g_P, nullptr, nullptr);
}
__global__ void __launch_bounds__(256, 2) gemm_score_kernel(const float* __restrict__ W1,
                                                            const float* __restrict__ b1,
                                                            const float* __restrict__ w2) {
    gemm128_body<N2H, N2H, 1>(g_Hout, W1, b1, nullptr, w2, g_spart);
}

// ---------------- cluster-8 recurrence, 2 CTAs/SM ----------------
// 256 CTAs = 32 clusters of 8. Cluster c: dir = c>>4, batches [(c&15)*4, +4).
// Rank r owns hidden cols [r*32, r*32+32). k-pairing with f32x2 (no packing in hot loop).
#define USTR 260
#define SM_UZ 0
#define SM_UH 8320
#define SM_H  16640               // [2][4][256] floats
#define SM_PP 18688               // u64[8ks][2g][4b][32kj] = 2048 u64 (16KB)
#define SMEM_GRU_BYTES ((SM_PP + 4096) * 4)   // 91136 B

__device__ __forceinline__ void st_cluster_f32(uint32_t addr, uint32_t rank, float v) {
    uint32_t ra;
    asm volatile("mapa.shared::cluster.u32 %0, %1, %2;" : "=r"(ra) : "r"(addr), "r"(rank));
    asm volatile("st.shared::cluster.f32 [%0], %1;" :: "r"(ra), "f"(v) : "memory");
}

__global__ void __launch_bounds__(256, 2) __cluster_dims__(8, 1, 1)
gru_kernel(const float* __restrict__ Uzf, const float* __restrict__ Uhf,
           const float* __restrict__ Uzb, const float* __restrict__ Uhb) {
    extern __shared__ __align__(16) float sm[];
    const int tid = threadIdx.x;
    uint32_t rank;
    asm("mov.u32 %0, %%cluster_ctarank;" : "=r"(rank));
    const int cid = blockIdx.x >> 3;
    const int dir = cid >> 4;
    const int b0 = (cid & 15) * 4;
    const int j0 = (int)rank * 32;
    const float* Uz = dir ? Uzb : Uzf;
    const float* Uh = dir ? Uhb : Uhf;

    float* sUz = sm + SM_UZ;
    float* sUh = sm + SM_UH;
    float* sh  = sm + SM_H;
    u64*   pp  = (u64*)(sm + SM_PP);

    // load U column slices transposed: sU[j][k] = U[k][j0+j]
    for (int i = tid; i < 32 * 256; i += 256) {
        int k = i >> 5;
        int j = i & 31;
        sUz[j * USTR + k] = Uz[k * HH + j0 + j];
        sUh[j * USTR + k] = Uh[k * HH + j0 + j];
    }
    __syncthreads();

    const int ks = tid >> 5;          // k-slice 0..7 (k in [ks*32, +32))
    const int kj = tid & 31;          // local column
    const int fb = (tid >> 5) & 3;    // finalize batch (tid<128)
    const int fj = tid & 31;          // finalize column
    const bool fin = tid < 128;

    const ulonglong2* uz4 = (const ulonglong2*)(sUz + kj * USTR + ks * 32);
    const ulonglong2* uh4 = (const ulonglong2*)(sUh + kj * USTR + ks * 32);
    uint32_t sh_u32 = (uint32_t)__cvta_generic_to_shared(sh);
    const uint32_t hoff_base = (uint32_t)(fb * 256 + j0 + fj) * 4u;

    float hself = 0.f;

    for (int t = 0; t < SS; ++t) {
        const int ts = dir ? (SS - 1 - t) : t;
        float xz = 0.f, xh = 0.f;
        if (fin) {
            const float* pr = &g_P[((size_t)(b0 + fb) * SS + ts) * NPROJ + dir * 512 + j0 + fj];
            xz = pr[0];
            xh = pr[HH];
        }

        if (t > 0) {
            const ulonglong2* hb = (const ulonglong2*)(sh + (((t & 1) ^ 1) << 10));
            u64 az0 = 0, az1 = 0, az2 = 0, az3 = 0;
            u64 ah0 = 0, ah1 = 0, ah2 = 0, ah3 = 0;
#pragma unroll
            for (int q = 0; q < 8; ++q) {
                ulonglong2 uz = uz4[q];
                ulonglong2 uh = uh4[q];
                ulonglong2 h0 = hb[0 * 64 + ks * 8 + q];
                ulonglong2 h1 = hb[1 * 64 + ks * 8 + q];
                ulonglong2 h2 = hb[2 * 64 + ks * 8 + q];
                ulonglong2 h3 = hb[3 * 64 + ks * 8 + q];
                FMA2(az0, uz.x, h0.x); FMA2(az0, uz.y, h0.y);
                FMA2(az1, uz.x, h1.x); FMA2(az1, uz.y, h1.y);
                FMA2(az2, uz.x, h2.x); FMA2(az2, uz.y, h2.y);
                FMA2(az3, uz.x, h3.x); FMA2(az3, uz.y, h3.y);
                FMA2(ah0, uh.x, h0.x); FMA2(ah0, uh.y, h0.y);
                FMA2(ah1, uh.x, h1.x); FMA2(ah1, uh.y, h1.y);
                FMA2(ah2, uh.x, h2.x); FMA2(ah2, uh.y, h2.y);
                FMA2(ah3, uh.x, h3.x); FMA2(ah3, uh.y, h3.y);
            }
            pp[((ks * 2 + 0) * 4 + 0) * 32 + kj] = az0;
            pp[((ks * 2 + 0) * 4 + 1) * 32 + kj] = az1;
            pp[((ks * 2 + 0) * 4 + 2) * 32 + kj] = az2;
            pp[((ks * 2 + 0) * 4 + 3) * 32 + kj] = az3;
            pp[((ks * 2 + 1) * 4 + 0) * 32 + kj] = ah0;
            pp[((ks * 2 + 1) * 4 + 1) * 32 + kj] = ah1;
            pp[((ks * 2 + 1) * 4 + 2) * 32 + kj] = ah2;
            pp[((ks * 2 + 1) * 4 + 3) * 32 + kj] = ah3;
        }
        __syncthreads();

        if (fin) {
            float az = xz, ah = xh;
            if (t > 0) {
                u64 sz = pp[(0 * 4 + fb) * 32 + fj];          // ks=0, g=0
                u64 shh = pp[(1 * 4 + fb) * 32 + fj];         // ks=0, g=1
#pragma unroll
                for (int s2 = 1; s2 < 8; ++s2) {
                    u64 vz = pp[((s2 * 2 + 0) * 4 + fb) * 32 + fj];
                    u64 vh = pp[((s2 * 2 + 1) * 4 + fb) * 32 + fj];
                    ADD2(sz, sz, vz);
                    ADD2(shh, shh, vh);
                }
                float lo, hi;
                UNPACK2(lo, hi, sz);  az += lo + hi;
                UNPACK2(lo, hi, shh); ah += lo + hi;
            }
            float z = fast_sigmoid(az);
            float hc = fast_tanh(ah);
            float hnew = fmaf(z, hself - hc, hc);
            hself = hnew;

            uint32_t loff = sh_u32 + ((uint32_t)(t & 1) << 12) + hoff_base;
#pragma unroll
            for (uint32_t r = 0; r < 8; ++r) st_cluster_f32(loff, r, hnew);

            g_Hout[((size_t)(b0 + fb) * SS + ts) * N2H + dir * HH + j0 + fj] = hnew;
        }

        asm volatile("barrier.cluster.arrive.aligned;" ::: "memory");
        asm volatile("barrier.cluster.wait.aligned;" ::: "memory");
    }
}

// ---------------- softmax over S ----------------
__global__ void __launch_bounds__(256) softmax_kernel() {
    __shared__ float sp[SS];
    __shared__ float rbuf[256];
    const int b = blockIdx.x;
    const int tid = threadIdx.x;

    float mx = -1e30f;
    for (int i = tid; i < SS; i += 256) {
        int row = b * SS + i;
        float v = g_spart[row] + g_spart[M_ROWS + row] +
                  g_spart[2 * M_ROWS + row] + g_spart[3 * M_ROWS + row];
        sp[i] = v;
        mx = fmaxf(mx, v);
    }
    rbuf[tid] = mx;
    __syncthreads();
#pragma unroll
    for (int o = 128; o > 0; o >>= 1) {
        if (tid < o) rbuf[tid] = fmaxf(rbuf[tid], rbuf[tid + o]);
        __syncthreads();
    }
    float m = rbuf[0];
    __syncthreads();

    float sum = 0.f;
    for (int i = tid; i < SS; i += 256) {
        float e = __expf(sp[i] - m);
        sp[i] = e;
        sum += e;
    }
    rbuf[tid] = sum;
    __syncthreads();
#pragma unroll
    for (int o = 128; o > 0; o >>= 1) {
        if (tid < o) rbuf[tid] += rbuf[tid + o];
        __syncthreads();
    }
    float inv = __fdividef(1.f, rbuf[0]);
    __syncthreads();
    for (int i = tid; i < SS; i += 256) g_attn[b * SS + i] = sp[i] * inv;
}

// ---------------- context ----------------
__global__ void __launch_bounds__(256) ctx_partial_kernel() {
    const int b = blockIdx.x;
    const int ch = blockIdx.y;
    const int tid = threadIdx.x;
    const float* hb = &g_Hout[((size_t)b * SS + ch * 128) * N2H];
    const float* ap = &g_attn[b * SS + ch * 128];
    float c0 = 0.f, c1 = 0.f;
    for (int s = 0; s < 128; ++s) {
        float p = ap[s];
        c0 = fmaf(p, hb[(size_t)s * N2H + tid], c0);
        c1 = fmaf(p, hb[(size_t)s * N2H + HH + tid], c1);
    }
    g_cpart[((size_t)ch * BB + b) * N2H + tid] = c0;
    g_cpart[((size_t)ch * BB + b) * N2H + HH + tid] = c1;
}

__global__ void __launch_bounds__(512) ctx_final_kernel(float* __restrict__ out) {
    const int b = blockIdx.x;
    const int tid = threadIdx.x;
    float s = 0.f;
#pragma unroll
    for (int ch = 0; ch < 8; ++ch)
        s += g_cpart[((size_t)ch * BB + b) * N2H + tid];
    out[b * N2H + tid] = s;
}

// ---------------- launcher ----------------
extern "C" void kernel_launch(void* const* d_in, const int* in_sizes, int n_in,
                              void* d_out, int out_size) {
    const float* x   = (const float*)d_in[0];
    const float* Wzf = (const float*)d_in[1];
    const float* Uzf = (const float*)d_in[2];
    const float* bzf = (const float*)d_in[3];
    const float* Whf = (const float*)d_in[4];
    const float* Uhf = (const float*)d_in[5];
    const float* bhf = (const float*)d_in[6];
    const float* Wzb = (const float*)d_in[7];
    const float* Uzb = (const float*)d_in[8];
    const float* bzb = (const float*)d_in[9];
    const float* Whb = (const float*)d_in[10];
    const float* Uhb = (const float*)d_in[11];
    const float* bhb = (const float*)d_in[12];
    const float* W1  = (const float*)d_in[13];
    const float* b1  = (const float*)d_in[14];
    const float* w2  = (const float*)d_in[15];
    float* out = (float*)d_out;

    cudaFuncSetAttribute(gru_kernel, cudaFuncAttributeMaxDynamicSharedMemorySize, SMEM_GRU_BYTES);

    pack_weights<<<512, 256>>>(Wzf, Whf, Wzb, Whb, bzf, bhf, bzb, bhb);
    gemm_proj_kernel<<<dim3(M_ROWS / 128, NPROJ / 128), 256>>>(x);
    gru_kernel<<<256, 256, SMEM_GRU_BYTES>>>(Uzf, Uhf, Uzb, Uhb);
    gemm_score_kernel<<<dim3(M_ROWS / 128, N2H / 128), 256>>>(W1, b1, w2);
    softmax_kernel<<<BB, 256>>>();
    ctx_partial_kernel<<<dim3(BB, 8), 256>>>();
    ctx_final_kernel<<<BB, 512>>>(out);
}

// round 5
// speedup vs baseline: 1.3115x; 1.3115x over previous
#include <cuda_runtime.h>
#include <math.h>
#include <stdint.h>

#define BB   64
#define SS   1024
#define DD   128
#define HH   256
#define M_ROWS (BB*SS)          // 65536
#define NPROJ  (4*HH)           // 1024
#define N2H    (2*HH)           // 512

// ---------------- device scratch ----------------
__device__ __align__(16) float g_P[(size_t)M_ROWS * NPROJ];
__device__ __align__(16) float g_Hout[(size_t)M_ROWS * N2H];
__device__ __align__(16) float g_Wcat[DD * NPROJ];
__device__ __align__(16) float g_bcat[NPROJ];
__device__ __align__(16) float g_spart[4 * M_ROWS];
__device__ __align__(16) float g_attn[M_ROWS];
__device__ __align__(16) float g_cpart[8 * BB * N2H];

__device__ __forceinline__ float fast_sigmoid(float x) {
    return __fdividef(1.f, 1.f + __expf(-x));
}
__device__ __forceinline__ float fast_tanh(float x) {
    return 1.f - __fdividef(2.f, __expf(2.f * x) + 1.f);
}
__device__ __forceinline__ uint32_t to_tf32(float f) {
    uint32_t u;
    asm("cvt.rna.tf32.f32 %0, %1;" : "=r"(u) : "f"(f));
    return u;
}
__device__ __forceinline__ void mma_tf32(float* d, const uint32_t* a, const uint32_t* b) {
    asm volatile("mma.sync.aligned.m16n8k8.row.col.f32.tf32.tf32.f32 "
                 "{%0,%1,%2,%3}, {%4,%5,%6,%7}, {%8,%9}, {%0,%1,%2,%3};"
                 : "+f"(d[0]), "+f"(d[1]), "+f"(d[2]), "+f"(d[3])
                 : "r"(a[0]), "r"(a[1]), "r"(a[2]), "r"(a[3]), "r"(b[0]), "r"(b[1]));
}

// ---------------- weight packing ----------------
__global__ void pack_weights(const float* __restrict__ Wzf, const float* __restrict__ Whf,
                             const float* __restrict__ Wzb, const float* __restrict__ Whb,
                             const float* __restrict__ bzf, const float* __restrict__ bhf,
                             const float* __restrict__ bzb, const float* __restrict__ bhb) {
    int idx = blockIdx.x * 256 + threadIdx.x;
    if (idx < DD * NPROJ) {
        int k = idx >> 10;
        int n = idx & 1023;
        int sel = n >> 8;
        int c = n & 255;
        const float* W = (sel == 0) ? Wzf : (sel == 1) ? Whf : (sel == 2) ? Wzb : Whb;
        g_Wcat[idx] = W[k * HH + c];
    }
    if (idx < NPROJ) {
        int sel = idx >> 8;
        int c = idx & 255;
        const float* bp = (sel == 0) ? bzf : (sel == 1) ? bhf : (sel == 2) ? bzb : bhb;
        g_bcat[idx] = bp[c];
    }
}

// ---------------- tf32 tensor-core GEMM, 128x128 tile, 256 threads (8 warps) ----------------
// Warps: 4 (m) x 2 (n). Each warp: m32 x n64 = 2 m16-frags x 8 n8-frags.
// As[k][132], Bs[k][132] tf32 bits (k-major, padded -> conflict-free frag loads).
// MODE 0: C = A@B + bias.  MODE 1: spart[by][row] = sum_c tanh(A@B+bias)[row,c]*w2[c].
template<int K, int N, int MODE>
__device__ __forceinline__ void gemm_tc_body(const float* __restrict__ A, const float* __restrict__ B,
                                             const float* __restrict__ bias, float* __restrict__ C,
                                             const float* __restrict__ w2, float* __restrict__ spart) {
    __shared__ __align__(16) uint32_t As[16][132];
    __shared__ __align__(16) uint32_t Bs[16][132];
    __shared__ float red[128][9];

    const int tid = threadIdx.x;
    const int m0 = blockIdx.x * 128;
    const int n0 = blockIdx.y * 128;
    const int warp = tid >> 5;
    const int lane = tid & 31;
    const int wm = warp & 3;          // m-warp: rows [wm*32, +32)
    const int wn = warp >> 2;         // n-warp: cols [wn*64, +64)
    const int g  = lane >> 2;         // 0..7
    const int tg = lane & 3;          // 0..3

    // staging roles
    const int arow = tid >> 2;        // rows arow, arow+64
    const int akq  = (tid & 3) * 4;   // k-quad
    const int bkr  = tid >> 5;        // k rows bkr, bkr+8
    const int bnq  = (tid & 31) * 4;

    float acc[2][8][4];
#pragma unroll
    for (int mf = 0; mf < 2; ++mf)
#pragma unroll
        for (int nf = 0; nf < 8; ++nf)
#pragma unroll
            for (int q = 0; q < 4; ++q) acc[mf][nf][q] = 0.f;

    const int NC = K / 16;
    float4 a0s = *(const float4*)&A[(size_t)(m0 + arow) * K + akq];
    float4 a1s = *(const float4*)&A[(size_t)(m0 + arow + 64) * K + akq];
    float4 b0s = *(const float4*)&B[(size_t)bkr * N + n0 + bnq];
    float4 b1s = *(const float4*)&B[(size_t)(bkr + 8) * N + n0 + bnq];

    for (int c = 0; c < NC; ++c) {
        __syncthreads();
        // store staged tiles (cvt to tf32)
        As[akq + 0][arow] = to_tf32(a0s.x);
        As[akq + 1][arow] = to_tf32(a0s.y);
        As[akq + 2][arow] = to_tf32(a0s.z);
        As[akq + 3][arow] = to_tf32(a0s.w);
        As[akq + 0][arow + 64] = to_tf32(a1s.x);
        As[akq + 1][arow + 64] = to_tf32(a1s.y);
        As[akq + 2][arow + 64] = to_tf32(a1s.z);
        As[akq + 3][arow + 64] = to_tf32(a1s.w);
        {
            uint4 v0 = make_uint4(to_tf32(b0s.x), to_tf32(b0s.y), to_tf32(b0s.z), to_tf32(b0s.w));
            uint4 v1 = make_uint4(to_tf32(b1s.x), to_tf32(b1s.y), to_tf32(b1s.z), to_tf32(b1s.w));
            *(uint4*)&Bs[bkr][bnq] = v0;
            *(uint4*)&Bs[bkr + 8][bnq] = v1;
        }
        // register prefetch of next stage
        if (c + 1 < NC) {
            int kb = (c + 1) * 16;
            a0s = *(const float4*)&A[(size_t)(m0 + arow) * K + kb + akq];
            a1s = *(const float4*)&A[(size_t)(m0 + arow + 64) * K + kb + akq];
            b0s = *(const float4*)&B[(size_t)(kb + bkr) * N + n0 + bnq];
            b1s = *(const float4*)&B[(size_t)(kb + bkr + 8) * N + n0 + bnq];
        }
        __syncthreads();
        // two k8 steps
#pragma unroll
        for (int kk = 0; kk < 16; kk += 8) {
            uint32_t af[2][4];
#pragma unroll
            for (int mf = 0; mf < 2; ++mf) {
                int mb = wm * 32 + mf * 16;
                af[mf][0] = As[kk + tg][mb + g];
                af[mf][1] = As[kk + tg][mb + g + 8];
                af[mf][2] = As[kk + tg + 4][mb + g];
                af[mf][3] = As[kk + tg + 4][mb + g + 8];
            }
            uint32_t bf[8][2];
#pragma unroll
            for (int nf = 0; nf < 8; ++nf) {
                int nb = wn * 64 + nf * 8;
                bf[nf][0] = Bs[kk + tg][nb + g];
                bf[nf][1] = Bs[kk + tg + 4][nb + g];
            }
#pragma unroll
            for (int mf = 0; mf < 2; ++mf)
#pragma unroll
                for (int nf = 0; nf < 8; ++nf)
                    mma_tf32(acc[mf][nf], af[mf], bf[nf]);
        }
    }

    if (MODE == 0) {
#pragma unroll
        for (int mf = 0; mf < 2; ++mf) {
            int row0 = m0 + wm * 32 + mf * 16 + g;
#pragma unroll
            for (int nf = 0; nf < 8; ++nf) {
                int col = n0 + wn * 64 + nf * 8 + tg * 2;
                float bv0 = bias[col];
                float bv1 = bias[col + 1];
                *(float2*)&C[(size_t)row0 * N + col] =
                    make_float2(acc[mf][nf][0] + bv0, acc[mf][nf][1] + bv1);
                *(float2*)&C[(size_t)(row0 + 8) * N + col] =
                    make_float2(acc[mf][nf][2] + bv0, acc[mf][nf][3] + bv1);
            }
        }
    } else {
        const int widx = wn * 4 + tg;
#pragma unroll
        for (int mf = 0; mf < 2; ++mf) {
            float p0 = 0.f, p1 = 0.f;
#pragma unroll
            for (int nf = 0; nf < 8; ++nf) {
                int col = n0 + wn * 64 + nf * 8 + tg * 2;
                float bv0 = bias[col];
                float bv1 = bias[col + 1];
                float w0 = w2[col];
                float w1 = w2[col + 1];
                p0 = fmaf(fast_tanh(acc[mf][nf][0] + bv0), w0, p0);
                p0 = fmaf(fast_tanh(acc[mf][nf][1] + bv1), w1, p0);
                p1 = fmaf(fast_tanh(acc[mf][nf][2] + bv0), w0, p1);
                p1 = fmaf(fast_tanh(acc[mf][nf][3] + bv1), w1, p1);
            }
            int r = wm * 32 + mf * 16 + g;
            red[r][widx] = p0;
            red[r + 8][widx] = p1;
        }
        __syncthreads();
        if (tid < 128) {
            float s = 0.f;
#pragma unroll
            for (int q = 0; q < 8; ++q) s += red[tid][q];
            spart[(size_t)blockIdx.y * M_ROWS + m0 + tid] = s;
        }
    }
}

__global__ void __launch_bounds__(256, 2) gemm_proj_kernel(const float* __restrict__ x) {
    gemm_tc_body<DD, NPROJ, 0>(x, g_Wcat, g_bcat, g_P, nullptr, nullptr);
}
__global__ void __launch_bounds__(256, 2) gemm_score_kernel(const float* __restrict__ W1,
                                                            const float* __restrict__ b1,
                                                            const float* __restrict__ w2) {
    gemm_tc_body<N2H, N2H, 1>(g_Hout, W1, b1, nullptr, w2, g_spart);
}

// ---------------- cluster-4 recurrence (known-good R3 version) ----------------
#define USTR 260
#define SM_UZ   0
#define SM_UH   (64 * USTR)
#define SM_H    (2 * 64 * USTR)            // [2][4][256]
#define SM_P    (SM_H + 2048)              // [4][2][4][64] partials
#define SMEM_GRU_FLOATS (SM_P + 2048)
#define SMEM_GRU_BYTES  (SMEM_GRU_FLOATS * 4)

__device__ __forceinline__ void st_cluster_f32(uint32_t addr, uint32_t rank, float v) {
    uint32_t ra;
    asm volatile("mapa.shared::cluster.u32 %0, %1, %2;" : "=r"(ra) : "r"(addr), "r"(rank));
    asm volatile("st.shared::cluster.f32 [%0], %1;" :: "r"(ra), "f"(v) : "memory");
}

__global__ void __launch_bounds__(256, 1) __cluster_dims__(4, 1, 1)
gru_kernel(const float* __restrict__ Uzf, const float* __restrict__ Uhf,
           const float* __restrict__ Uzb, const float* __restrict__ Uhb) {
    extern __shared__ __align__(16) float sm[];
    const int tid = threadIdx.x;
    uint32_t rank;
    asm("mov.u32 %0, %%cluster_ctarank;" : "=r"(rank));
    const int cidx = blockIdx.x >> 2;
    const int dir = cidx >> 4;
    const int b0 = (cidx & 15) * 4;
    const int j0 = (int)rank * 64;
    const float* Uz = dir ? Uzb : Uzf;
    const float* Uh = dir ? Uhb : Uhf;

    float* sUz = sm + SM_UZ;
    float* sUh = sm + SM_UH;
    float* sh  = sm + SM_H;
    float* pp  = sm + SM_P;

    for (int i = tid; i < 64 * 256; i += 256) {
        int k = i >> 6;
        int j = i & 63;
        sUz[j * USTR + k] = Uz[k * HH + j0 + j];
        sUh[j * USTR + k] = Uh[k * HH + j0 + j];
    }
    __syncthreads();

    const int kj = tid & 63;
    const int ks = tid >> 6;
    const int fb = tid >> 6;
    const int fj = tid & 63;

    const float4* sUz4 = (const float4*)(sUz + kj * USTR + ks * 64);
    const float4* sUh4 = (const float4*)(sUh + kj * USTR + ks * 64);

    uint32_t sh_u32 = (uint32_t)__cvta_generic_to_shared(sh);
    const uint32_t hoff_base = ((uint32_t)(fb * 256 + j0 + fj)) * 4u;

    float hself = 0.f;

    for (int t = 0; t < SS; ++t) {
        const int ts = dir ? (SS - 1 - t) : t;
        const size_t prow = ((size_t)(b0 + fb) * SS + ts) * NPROJ + dir * 512 + j0 + fj;
        const float xz = g_P[prow];
        const float xh = g_P[prow + HH];

        float az, ah;
        if (t > 0) {
            const float4* hb = (const float4*)(sh + (((t & 1) ^ 1) << 10));
            float a0 = 0.f, a1 = 0.f, a2 = 0.f, a3 = 0.f;
            float c0 = 0.f, c1 = 0.f, c2 = 0.f, c3 = 0.f;
#pragma unroll
            for (int q = 0; q < 16; ++q) {
                float4 uz = sUz4[q];
                float4 uh = sUh4[q];
                int kq = ks * 16 + q;
                float4 h0 = hb[0 * 64 + kq];
                float4 h1 = hb[1 * 64 + kq];
                float4 h2 = hb[2 * 64 + kq];
                float4 h3 = hb[3 * 64 + kq];
                a0 = fmaf(uz.x, h0.x, a0); a0 = fmaf(uz.y, h0.y, a0);
                a0 = fmaf(uz.z, h0.z, a0); a0 = fmaf(uz.w, h0.w, a0);
                a1 = fmaf(uz.x, h1.x, a1); a1 = fmaf(uz.y, h1.y, a1);
                a1 = fmaf(uz.z, h1.z, a1); a1 = fmaf(uz.w, h1.w, a1);
                a2 = fmaf(uz.x, h2.x, a2); a2 = fmaf(uz.y, h2.y, a2);
                a2 = fmaf(uz.z, h2.z, a2); a2 = fmaf(uz.w, h2.w, a2);
                a3 = fmaf(uz.x, h3.x, a3); a3 = fmaf(uz.y, h3.y, a3);
                a3 = fmaf(uz.z, h3.z, a3); a3 = fmaf(uz.w, h3.w, a3);
                c0 = fmaf(uh.x, h0.x, c0); c0 = fmaf(uh.y, h0.y, c0);
                c0 = fmaf(uh.z, h0.z, c0); c0 = fmaf(uh.w, h0.w, c0);
                c1 = fmaf(uh.x, h1.x, c1); c1 = fmaf(uh.y, h1.y, c1);
                c1 = fmaf(uh.z, h1.z, c1); c1 = fmaf(uh.w, h1.w, c1);
                c2 = fmaf(uh.x, h2.x, c2); c2 = fmaf(uh.y, h2.y, c2);
                c2 = fmaf(uh.z, h2.z, c2); c2 = fmaf(uh.w, h2.w, c2);
                c3 = fmaf(uh.x, h3.x, c3); c3 = fmaf(uh.y, h3.y, c3);
                c3 = fmaf(uh.z, h3.z, c3); c3 = fmaf(uh.w, h3.w, c3);
            }
            pp[ks * 512 +   0 + 0 * 64 + kj] = a0;
            pp[ks * 512 +   0 + 1 * 64 + kj] = a1;
            pp[ks * 512 +   0 + 2 * 64 + kj] = a2;
            pp[ks * 512 +   0 + 3 * 64 + kj] = a3;
            pp[ks * 512 + 256 + 0 * 64 + kj] = c0;
            pp[ks * 512 + 256 + 1 * 64 + kj] = c1;
            pp[ks * 512 + 256 + 2 * 64 + kj] = c2;
            pp[ks * 512 + 256 + 3 * 64 + kj] = c3;
            __syncthreads();
            az = xz;
            ah = xh;
#pragma unroll
            for (int s2 = 0; s2 < 4; ++s2) {
                az += pp[s2 * 512 + fb * 64 + fj];
                ah += pp[s2 * 512 + 256 + fb * 64 + fj];
            }
        } else {
            az = xz;
            ah = xh;
        }

        float z = fast_sigmoid(az);
        float hc = fast_tanh(ah);
        float hnew = fmaf(z, hself - hc, hc);
        hself = hnew;

        uint32_t loff = sh_u32 + ((uint32_t)(t & 1) << 12) + hoff_base;
#pragma unroll
        for (uint32_t r = 0; r < 4; ++r) st_cluster_f32(loff, r, hnew);

        g_Hout[((size_t)(b0 + fb) * SS + ts) * N2H + dir * HH + j0 + fj] = hnew;

        asm volatile("barrier.cluster.arrive.aligned;" ::: "memory");
        asm volatile("barrier.cluster.wait.aligned;" ::: "memory");
    }
}

// ---------------- softmax over S ----------------
__global__ void __launch_bounds__(256) softmax_kernel() {
    __shared__ float sp[SS];
    __shared__ float rbuf[256];
    const int b = blockIdx.x;
    const int tid = threadIdx.x;

    float mx = -1e30f;
    for (int i = tid; i < SS; i += 256) {
        int row = b * SS + i;
        float v = g_spart[row] + g_spart[M_ROWS + row] +
                  g_spart[2 * M_ROWS + row] + g_spart[3 * M_ROWS + row];
        sp[i] = v;
        mx = fmaxf(mx, v);
    }
    rbuf[tid] = mx;
    __syncthreads();
#pragma unroll
    for (int o = 128; o > 0; o >>= 1) {
        if (tid < o) rbuf[tid] = fmaxf(rbuf[tid], rbuf[tid + o]);
        __syncthreads();
    }
    float m = rbuf[0];
    __syncthreads();

    float sum = 0.f;
    for (int i = tid; i < SS; i += 256) {
        float e = __expf(sp[i] - m);
        sp[i] = e;
        sum += e;
    }
    rbuf[tid] = sum;
    __syncthreads();
#pragma unroll
    for (int o = 128; o > 0; o >>= 1) {
        if (tid < o) rbuf[tid] += rbuf[tid + o];
        __syncthreads();
    }
    float inv = __fdividef(1.f, rbuf[0]);
    __syncthreads();
    for (int i = tid; i < SS; i += 256) g_attn[b * SS + i] = sp[i] * inv;
}

// ---------------- context ----------------
__global__ void __launch_bounds__(256) ctx_partial_kernel() {
    const int b = blockIdx.x;
    const int ch = blockIdx.y;
    const int tid = threadIdx.x;
    const float* hb = &g_Hout[((size_t)b * SS + ch * 128) * N2H];
    const float* ap = &g_attn[b * SS + ch * 128];
    float c0 = 0.f, c1 = 0.f;
    for (int s = 0; s < 128; ++s) {
        float p = ap[s];
        c0 = fmaf(p, hb[(size_t)s * N2H + tid], c0);
        c1 = fmaf(p, hb[(size_t)s * N2H + HH + tid], c1);
    }
    g_cpart[((size_t)ch * BB + b) * N2H + tid] = c0;
    g_cpart[((size_t)ch * BB + b) * N2H + HH + tid] = c1;
}

__global__ void __launch_bounds__(512) ctx_final_kernel(float* __restrict__ out) {
    const int b = blockIdx.x;
    const int tid = threadIdx.x;
    float s = 0.f;
#pragma unroll
    for (int ch = 0; ch < 8; ++ch)
        s += g_cpart[((size_t)ch * BB + b) * N2H + tid];
    out[b * N2H + tid] = s;
}

// ---------------- launcher ----------------
extern "C" void kernel_launch(void* const* d_in, const int* in_sizes, int n_in,
                              void* d_out, int out_size) {
    const float* x   = (const float*)d_in[0];
    const float* Wzf = (const float*)d_in[1];
    const float* Uzf = (const float*)d_in[2];
    const float* bzf = (const float*)d_in[3];
    const float* Whf = (const float*)d_in[4];
    const float* Uhf = (const float*)d_in[5];
    const float* bhf = (const float*)d_in[6];
    const float* Wzb = (const float*)d_in[7];
    const float* Uzb = (const float*)d_in[8];
    const float* bzb = (const float*)d_in[9];
    const float* Whb = (const float*)d_in[10];
    const float* Uhb = (const float*)d_in[11];
    const float* bhb = (const float*)d_in[12];
    const float* W1  = (const float*)d_in[13];
    const float* b1  = (const float*)d_in[14];
    const float* w2  = (const float*)d_in[15];
    float* out = (float*)d_out;

    cudaFuncSetAttribute(gru_kernel, cudaFuncAttributeMaxDynamicSharedMemorySize, SMEM_GRU_BYTES);

    pack_weights<<<512, 256>>>(Wzf, Whf, Wzb, Whb, bzf, bhf, bzb, bhb);
    gemm_proj_kernel<<<dim3(M_ROWS / 128, NPROJ / 128), 256>>>(x);
    gru_kernel<<<128, 256, SMEM_GRU_BYTES>>>(Uzf, Uhf, Uzb, Uhb);
    gemm_score_kernel<<<dim3(M_ROWS / 128, N2H / 128), 256>>>(W1, b1, w2);
    softmax_kernel<<<BB, 256>>>();
    ctx_partial_kernel<<<dim3(BB, 8), 256>>>();
    ctx_final_kernel<<<BB, 512>>>(out);
}